// round 12
// baseline (speedup 1.0000x reference)
#include <cuda_runtime.h>
#include <cuda_fp16.h>
#include <cstdint>

#define NB    32
#define CIN   64
#define COUT  128
#define HDIM  64
#define WDIM  64
#define EPSV  1e-8f
#define FM_OFF (NB * COUT * HDIM * WDIM)
#define NT4   8192                // tiles: 32 n * 16 ty * 16 tx (4x4 outputs)
#define NPOS  36
#define WSC   256.0f              // weight plane scale
#define IWSC  0.00390625f         // 1/256

// ---- scratch (static __device__, no allocations) ----
__device__ float g_inv_norm[COUT];
__device__ __align__(128) __half g_Xh[NPOS][NT4][64];   // [pos][tile][ci]
__device__ __align__(128) __half g_Xl[NPOS][NT4][64];
__device__ __align__(128) __half g_Wh[NPOS][64][128];   // [pos][ci][co], x256
__device__ __align__(128) __half g_Wl[NPOS][64][128];
__device__ float g_M[NPOS * NT4 * 128];                 // [pos][tile][co]

// ---- helpers ----
__device__ __forceinline__ void cpa16(uint32_t dst, const void* src) {
    asm volatile("cp.async.ca.shared.global [%0], [%1], 16;" :: "r"(dst), "l"(src));
}
__device__ __forceinline__ void cpcommit() {
    asm volatile("cp.async.commit_group;" ::: "memory");
}
template <int N>
__device__ __forceinline__ void cpwait() {
    asm volatile("cp.async.wait_group %0;" :: "n"(N) : "memory");
}
__device__ __forceinline__ void ldsm_x4(uint32_t* r, uint32_t a) {
    asm volatile("ldmatrix.sync.aligned.m8n8.x4.shared.b16 {%0,%1,%2,%3}, [%4];"
                 : "=r"(r[0]), "=r"(r[1]), "=r"(r[2]), "=r"(r[3]) : "r"(a));
}
__device__ __forceinline__ void ldsm_x4t(uint32_t* r, uint32_t a) {
    asm volatile("ldmatrix.sync.aligned.m8n8.x4.trans.shared.b16 {%0,%1,%2,%3}, [%4];"
                 : "=r"(r[0]), "=r"(r[1]), "=r"(r[2]), "=r"(r[3]) : "r"(a));
}
__device__ __forceinline__ void mma16(float* d, const uint32_t* a, uint32_t b0,
                                      uint32_t b1) {
    asm volatile(
        "mma.sync.aligned.m16n8k16.row.col.f32.f16.f16.f32 "
        "{%0,%1,%2,%3},{%4,%5,%6,%7},{%8,%9},{%0,%1,%2,%3};"
        : "+f"(d[0]), "+f"(d[1]), "+f"(d[2]), "+f"(d[3])
        : "r"(a[0]), "r"(a[1]), "r"(a[2]), "r"(a[3]), "r"(b0), "r"(b1));
}

// ---------- prep: per-Cout 1/(||k||^2 + eps) ----------
__global__ void prep_norm(const float* __restrict__ kern) {
    __shared__ float red[512];
    int t = threadIdx.x;
    int co = t & 127;
    int part = t >> 7;
    float s = 0.f;
#pragma unroll 4
    for (int i = part * 144; i < part * 144 + 144; i++) {
        float v = kern[i * COUT + co];
        s += v * v;
    }
    red[t] = s;
    __syncthreads();
    if (t < 128)
        g_inv_norm[co] = 1.f / (red[co] + red[co + 128] + red[co + 256] + red[co + 384] + EPSV);
}

// ---------- prep: F(4,3) weight transform W~ = (G g G^T) * 256, fp16 hi/lo ----------
// G = [[1/4,0,0],[-1/6,-1/6,-1/6],[-1/6,1/6,-1/6],[1/24,1/12,1/6],[1/24,-1/12,1/6],[0,0,1]]
__global__ void prep_Wt(const float* __restrict__ kern) {
    int id = blockIdx.x * 256 + threadIdx.x;   // 8192
    int co = id & 127;
    int ci = id >> 7;

    float g[3][3];
#pragma unroll
    for (int kh = 0; kh < 3; kh++)
#pragma unroll
        for (int kw = 0; kw < 3; kw++)
            g[kh][kw] = kern[(kh * 3 + kw) * (CIN * COUT) + ci * COUT + co];

    float t[6][3];
#pragma unroll
    for (int c = 0; c < 3; c++) {
        t[0][c] = 0.25f * g[0][c];
        t[1][c] = -(g[0][c] + g[1][c] + g[2][c]) * (1.f / 6.f);
        t[2][c] = (-g[0][c] + g[1][c] - g[2][c]) * (1.f / 6.f);
        t[3][c] = g[0][c] * (1.f / 24.f) + g[1][c] * (1.f / 12.f) + g[2][c] * (1.f / 6.f);
        t[4][c] = g[0][c] * (1.f / 24.f) - g[1][c] * (1.f / 12.f) + g[2][c] * (1.f / 6.f);
        t[5][c] = g[2][c];
    }
#pragma unroll
    for (int i = 0; i < 6; i++) {
        float w[6];
        w[0] = 0.25f * t[i][0];
        w[1] = -(t[i][0] + t[i][1] + t[i][2]) * (1.f / 6.f);
        w[2] = (-t[i][0] + t[i][1] - t[i][2]) * (1.f / 6.f);
        w[3] = t[i][0] * (1.f / 24.f) + t[i][1] * (1.f / 12.f) + t[i][2] * (1.f / 6.f);
        w[4] = t[i][0] * (1.f / 24.f) - t[i][1] * (1.f / 12.f) + t[i][2] * (1.f / 6.f);
        w[5] = t[i][2];
#pragma unroll
        for (int j = 0; j < 6; j++) {
            int p = i * 6 + j;
            float v = w[j] * WSC;
            __half h = __float2half(v);
            __half l = __float2half(v - __half2float(h));
            g_Wh[p][ci][co] = h;
            g_Wl[p][ci][co] = l;
        }
    }
}

// ---------- prep: F(4,3) input transform X~ = B^T d B, smem-staged ----------
// B^T rows: [4,0,-5,0,1,0],[0,-4,-4,1,1,0],[0,4,-4,-1,1,0],
//           [0,-2,-1,2,1,0],[0,2,-1,-2,1,0],[0,4,0,-5,0,1]
#define XSP4 66
#define XT4_SMEM (6 * 64 * XSP4 * 4)
__global__ __launch_bounds__(256)
void prep_Xt(const float* __restrict__ x) {
    extern __shared__ float xs[];
    const int n = blockIdx.x >> 4;
    const int ty = blockIdx.x & 15;
    const int tid = threadIdx.x;
    const int w = tid >> 5;
    const int l = tid & 31;

    // phase 1: coalesced load 64ci x 6rows x 64cols into [r][c][ci pitch 66]
#pragma unroll
    for (int i = 0; i < 96; i++) {
        int idx = tid + i * 256;
        int ci = idx / 384;
        int rem = idx - ci * 384;
        int r = rem >> 6;
        int c = rem & 63;
        int gr = 4 * ty - 1 + r;
        float v = (gr >= 0 && gr < HDIM)
                      ? __ldg(x + ((n * CIN + ci) * HDIM + gr) * WDIM + c)
                      : 0.f;
        xs[(r * 64 + c) * XSP4 + ci] = v;
    }
    __syncthreads();

#pragma unroll 1
    for (int it = 0; it < 4; it++) {
        const int unit = it * 8 + w;      // 32 units = 16 tx x 2 ci-halves
        const int tx = unit & 15;
        const int ci = (unit >> 4) * 32 + l;
        const int tile = n * 256 + ty * 16 + tx;
        const int wb = 4 * tx - 1;

        float s[6][6];
#pragma unroll
        for (int c = 0; c < 6; c++) {
            int gc = wb + c;
            float d0 = 0.f, d1 = 0.f, d2 = 0.f, d3 = 0.f, d4 = 0.f, d5 = 0.f;
            if (gc >= 0 && gc < WDIM) {   // warp-uniform branch
                const float* col = &xs[gc * XSP4 + ci];
                d0 = col[0 * 64 * XSP4]; d1 = col[1 * 64 * XSP4];
                d2 = col[2 * 64 * XSP4]; d3 = col[3 * 64 * XSP4];
                d4 = col[4 * 64 * XSP4]; d5 = col[5 * 64 * XSP4];
            }
            s[0][c] = 4.f * d0 - 5.f * d2 + d4;
            s[1][c] = -4.f * d1 - 4.f * d2 + d3 + d4;
            s[2][c] = 4.f * d1 - 4.f * d2 - d3 + d4;
            s[3][c] = -2.f * d1 - d2 + 2.f * d3 + d4;
            s[4][c] = 2.f * d1 - d2 - 2.f * d3 + d4;
            s[5][c] = 4.f * d1 - 5.f * d3 + d5;
        }
#pragma unroll
        for (int i = 0; i < 6; i++) {
            float v[6];
            v[0] = 4.f * s[i][0] - 5.f * s[i][2] + s[i][4];
            v[1] = -4.f * s[i][1] - 4.f * s[i][2] + s[i][3] + s[i][4];
            v[2] = 4.f * s[i][1] - 4.f * s[i][2] - s[i][3] + s[i][4];
            v[3] = -2.f * s[i][1] - s[i][2] + 2.f * s[i][3] + s[i][4];
            v[4] = 2.f * s[i][1] - s[i][2] - 2.f * s[i][3] + s[i][4];
            v[5] = 4.f * s[i][1] - 5.f * s[i][3] + s[i][5];
#pragma unroll
            for (int j = 0; j < 6; j++) {
                int p = i * 6 + j;
                __half h = __float2half(v[j]);
                __half lo = __float2half(v[j] - __half2float(h));
                g_Xh[p][tile][ci] = h;
                g_Xl[p][tile][ci] = lo;
            }
        }
    }
}

// ---------- GEMM per pos: M~[tile][co] = X~ . W~ (3 planes, single fp32 acc) ----------
// smem: Ah 0 (128x144), Al 18432, Bh 36864 (64x272), Bl 54272; total 71680
#define G4_SMEM 71680
__global__ __launch_bounds__(256, 2)
void gemm4() {
    extern __shared__ char smc[];
    const uint32_t smu = (uint32_t)__cvta_generic_to_shared(smc);
    const int tid = threadIdx.x;
    const int lane = tid & 31;
    const int wrp = tid >> 5;
    const int mw = wrp & 3;           // 4 M-warps x 32 rows
    const int nw = wrp >> 2;          // 2 N-warps x 64 co
    const int pos = blockIdx.x >> 6;
    const int TB = (blockIdx.x & 63) << 7;   // tile base (128 per CTA)

    // stage A (both planes)
#pragma unroll
    for (int i = 0; i < 8; i++) {
        int idx = tid + i * 256;
        int pl = idx >> 10;
        int q = idx & 1023;
        int r = q >> 3, c = q & 7;
        cpa16(smu + pl * 18432 + r * 144 + c * 16,
              (pl ? g_Xl[pos][TB + r] : g_Xh[pos][TB + r]) + c * 8);
    }
    // stage B (both planes)
#pragma unroll
    for (int i = 0; i < 8; i++) {
        int idx = tid + i * 256;
        int pl = idx >> 10;
        int q = idx & 1023;
        int r = q >> 4, c = q & 15;
        cpa16(smu + 36864 + pl * 17408 + r * 272 + c * 16,
              (pl ? g_Wl[pos][r] : g_Wh[pos][r]) + c * 8);
    }
    cpcommit();
    cpwait<0>();
    __syncthreads();

    float acc[2][4][2][4];            // [mb][nb][n8-half][frag]
#pragma unroll
    for (int a = 0; a < 2; a++)
#pragma unroll
        for (int b = 0; b < 4; b++)
#pragma unroll
            for (int h = 0; h < 2; h++)
#pragma unroll
                for (int k = 0; k < 4; k++) acc[a][b][h][k] = 0.f;

    const uint32_t aoff = (uint32_t)(lane & 15) * 144 + (uint32_t)(lane >> 4) * 16;
    const uint32_t boff = (uint32_t)(lane & 15) * 272 +
                          (uint32_t)(nw * 64 + (lane >> 4) * 8) * 2;

#pragma unroll
    for (int kb = 0; kb < 4; kb++) {
        uint32_t ah[2][4], al[2][4];
#pragma unroll
        for (int mb = 0; mb < 2; mb++) {
            uint32_t aa = smu + (uint32_t)(mw * 32 + mb * 16) * 144 + aoff + kb * 32;
            ldsm_x4(ah[mb], aa);
            ldsm_x4(al[mb], aa + 18432);
        }
#pragma unroll
        for (int nb = 0; nb < 4; nb++) {
            uint32_t ba = smu + 36864 + (uint32_t)(kb * 16) * 272 + boff + nb * 32;
            uint32_t bh[4], bl[4];
            ldsm_x4t(bh, ba);
            ldsm_x4t(bl, ba + 17408);
#pragma unroll
            for (int mb = 0; mb < 2; mb++) {
                mma16(acc[mb][nb][0], ah[mb], bh[0], bh[1]);
                mma16(acc[mb][nb][1], ah[mb], bh[2], bh[3]);
                mma16(acc[mb][nb][0], al[mb], bh[0], bh[1]);
                mma16(acc[mb][nb][1], al[mb], bh[2], bh[3]);
                mma16(acc[mb][nb][0], ah[mb], bl[0], bl[1]);
                mma16(acc[mb][nb][1], ah[mb], bl[2], bl[3]);
            }
        }
    }

    // write m~ [pos][tile][co]
    float* gm = g_M + (pos * NT4 + TB) * 128;
    const int r0 = lane >> 2;
    const int c0 = 2 * (lane & 3);
#pragma unroll
    for (int mb = 0; mb < 2; mb++)
#pragma unroll
        for (int nb = 0; nb < 4; nb++)
#pragma unroll
            for (int h = 0; h < 2; h++)
#pragma unroll
                for (int rr = 0; rr < 2; rr++) {
                    int row = mw * 32 + mb * 16 + r0 + rr * 8;
                    int col = nw * 64 + nb * 16 + h * 8 + c0;
                    *(float2*)(gm + row * 128 + col) =
                        make_float2(acc[mb][nb][h][rr * 2], acc[mb][nb][h][rr * 2 + 1]);
                }
}

// ---------- output: conv = (A^T M A)/256, fused LIF + multi-threshold spike ----------
// A^T = [[1,1,1,1,1,0],[0,1,-1,2,-2,0],[0,1,1,4,4,0],[0,1,-1,8,-8,1]]
#define MSLP 261
#define OSLP 264
#define OSS  (32 * OSLP)
#define OS_SMEM ((32 * MSLP + 2 * OSS) * 4)
__global__ __launch_bounds__(256, 2)
void out_spike(const float* __restrict__ mem, const float* __restrict__ beta_p,
               const float* __restrict__ b_p, float* __restrict__ out) {
    extern __shared__ float sms[];
    float* msl = sms;                 // [32 co][4 h][64 w], co pitch 261
    float* osl = sms + 32 * MSLP;     // [2][32 co][4 h][64 w], co pitch 264
    const int tid = threadIdx.x;
    const int cb = blockIdx.x & 3;
    const int ty = (blockIdx.x >> 2) & 15;
    const int n = blockIdx.x >> 6;

    // phase A: stage mem slab (coalesced)
#pragma unroll
    for (int i = 0; i < 32; i++) {
        int idx = tid + i * 256;
        int col = idx >> 8;
        int h = (idx >> 6) & 3;
        int w = idx & 63;
        msl[col * MSLP + h * 64 + w] =
            __ldg(mem + ((n * COUT + cb * 32 + col) * HDIM + 4 * ty + h) * WDIM + w);
    }
    __syncthreads();

    const float beta = beta_p[0];
    const float omb = 1.f - beta;

    // phase B: per (tx, co) pair: read 36 m~, transform, LIF, stage outputs
#pragma unroll 1
    for (int pi = 0; pi < 2; pi++) {
        const int pp = tid + pi * 256;
        const int tx = pp >> 5;
        const int col = pp & 31;
        const int co = cb * 32 + col;
        const int tile = n * 256 + ty * 16 + tx;
        const float* gm = g_M + tile * 128 + co;

        float m[36];
#pragma unroll
        for (int p = 0; p < 36; p++) m[p] = __ldg(gm + p * (NT4 * 128));

        float t4[4][6];
#pragma unroll
        for (int j = 0; j < 6; j++) {
            float m1 = m[6 + j], m2 = m[12 + j], m3 = m[18 + j], m4 = m[24 + j];
            t4[0][j] = m[j] + m1 + m2 + m3 + m4;
            t4[1][j] = m1 - m2 + 2.f * (m3 - m4);
            t4[2][j] = m1 + m2 + 4.f * (m3 + m4);
            t4[3][j] = m1 - m2 + 8.f * (m3 - m4) + m[30 + j];
        }
        const float invn = g_inv_norm[co];
        const float bb = b_p[co];
#pragma unroll
        for (int r = 0; r < 4; r++) {
            float t1 = t4[r][1], t2 = t4[r][2], t3 = t4[r][3], t5 = t4[r][4];
            float ov[4];
            ov[0] = t4[r][0] + t1 + t2 + t3 + t5;
            ov[1] = t1 - t2 + 2.f * (t3 - t5);
            ov[2] = t1 + t2 + 4.f * (t3 + t5);
            ov[3] = t1 - t2 + 8.f * (t3 - t5) + t4[r][5];
#pragma unroll
            for (int c = 0; c < 4; c++) {
                float conv = ov[c] * IWSC;
                float nm = msl[col * MSLP + r * 64 + 4 * tx + c] * beta + conv * omb;
                float mt = nm * invn - bb;
                float cnt =
                    (float)((mt > 0.f) + (mt > 1.f) + (mt > 2.f) + (mt > 3.f));
                osl[col * OSLP + r * 64 + 4 * tx + c] = cnt;
                osl[OSS + col * OSLP + r * 64 + 4 * tx + c] = (cnt > 0.f) ? 0.f : nm;
            }
        }
    }
    __syncthreads();

    // phase C: coalesced writes (spk then final_mem)
#pragma unroll
    for (int i = 0; i < 16; i++) {
        int idx = tid + i * 256;
        int chunk = idx & 15;
        int row = idx >> 4;               // 256 rows = 2 out x 32 co x 4 h
        int h = row & 3;
        int col = (row >> 2) & 31;
        int o = row >> 7;
        float4 v = *(float4*)&osl[o * OSS + col * OSLP + h * 64 + chunk * 4];
        *(float4*)(out + o * FM_OFF +
                   ((n * COUT + cb * 32 + col) * HDIM + 4 * ty + h) * WDIM +
                   chunk * 4) = v;
    }
}

extern "C" void kernel_launch(void* const* d_in, const int* in_sizes, int n_in,
                              void* d_out, int out_size) {
    const float* x    = (const float*)d_in[0];
    const float* mem  = (const float*)d_in[1];
    const float* kern = (const float*)d_in[2];
    const float* beta = (const float*)d_in[3];
    const float* b    = (const float*)d_in[4];
    float* out = (float*)d_out;

    cudaFuncSetAttribute(prep_Xt, cudaFuncAttributeMaxDynamicSharedMemorySize, XT4_SMEM);
    cudaFuncSetAttribute(gemm4, cudaFuncAttributeMaxDynamicSharedMemorySize, G4_SMEM);
    cudaFuncSetAttribute(out_spike, cudaFuncAttributeMaxDynamicSharedMemorySize, OS_SMEM);

    prep_norm<<<1, 512>>>(kern);
    prep_Wt<<<32, 256>>>(kern);
    prep_Xt<<<512, 256, XT4_SMEM>>>(x);
    gemm4<<<NPOS * 64, 256, G4_SMEM>>>();
    out_spike<<<2048, 256, OS_SMEM>>>(mem, beta, b, out);
}